// round 10
// baseline (speedup 1.0000x reference)
#include <cuda_runtime.h>
#include <cstdint>

// Problem-instance constants (fixed by setup_inputs)
#define N_ENT   200000
#define N_REL   500
#define BATCH   64
#define NWORDS  16                 // 512 bits >= 500 relations
#define MASKW   (N_ENT / 32)       // 6250 mask words per query
#define MAXK    16
#define CAND    256                // candidates per main CTA
#define NCHUNKS ((N_ENT + CAND - 1) / CAND)   // 782
#define CSTRIDE 257                // padded smem stride
#define FCAP    4096               // final survivor buffer (= full rescan size)

// ---------------- device scratch (no allocations allowed) ----------------
__device__ uint32_t g_qw[BATCH * NWORDS];            // query bitmaps
__device__ float    g_sq[BATCH];                     // s_q
__device__ uint32_t g_mask[(size_t)BATCH * MASKW];   // keep bits
__device__ uint32_t g_cmax[(size_t)BATCH * NCHUNKS]; // chunk-max ord (u32)

// ord = keep ? bits|0x80000000 : 0   (vals >= 0, so this is order-preserving)
__device__ __forceinline__ uint32_t u32max_(uint32_t a, uint32_t b) {
    return a > b ? a : b;
}

// Binarize 4 preloaded float4 chunks of one row into this lane's 4-bit nibbles,
// merge via butterfly shuffles; returns per-chunk combined words v[4].
// Word (4c + g) of the row is v[c] on lanes with (lane>>3)==g, (lane&7)==0.
__device__ __forceinline__ void pack_row_regs(const float4 f[4], int lane,
                                              uint32_t v[4]) {
    #pragma unroll
    for (int c = 0; c < 4; ++c) {
        uint32_t nib = (f[c].x != 0.0f ? 1u : 0u) | (f[c].y != 0.0f ? 2u : 0u)
                     | (f[c].z != 0.0f ? 4u : 0u) | (f[c].w != 0.0f ? 8u : 0u);
        uint32_t t = nib;
        #pragma unroll
        for (int s = 0; s < 3; ++s) {
            const int step = 1 << s;
            const int w = 4 << s;
            uint32_t other = __shfl_xor_sync(0xffffffffu, t, step);
            t = (lane & step) ? ((t << w) | other) : (t | (other << w));
        }
        v[c] = t;
    }
}

// Load one row's 4 float4 chunks (lane-strided); OOB -> zero.
__device__ __forceinline__ void load_row_f4(const float* __restrict__ row,
                                            bool rowValid, int lane, float4 f[4]) {
    #pragma unroll
    for (int c = 0; c < 4; ++c) {
        const int e = c * 128 + lane * 4;
        if (rowValid && e + 3 < N_REL)
            f[c] = *(const float4*)(row + e);
        else
            f[c] = make_float4(0.f, 0.f, 0.f, 0.f);
    }
}

// ============================================================================
// 0) qpack: 64 CTAs x 128 threads; warp c packs chunk c of the query row.
// ============================================================================
__global__ void __launch_bounds__(128)
qpack_kernel(const float* __restrict__ ev, const int* __restrict__ qent) {
    const int b    = blockIdx.x;
    const int warp = threadIdx.x >> 5;
    const int lane = threadIdx.x & 31;
    const float* row = ev + (size_t)qent[b] * N_REL;
    const int e = warp * 128 + lane * 4;
    float4 f = make_float4(0.f, 0.f, 0.f, 0.f);
    if (e + 3 < N_REL) f = *(const float4*)(row + e);
    uint32_t nib = (f.x != 0.0f ? 1u : 0u) | (f.y != 0.0f ? 2u : 0u)
                 | (f.z != 0.0f ? 4u : 0u) | (f.w != 0.0f ? 8u : 0u);
    uint32_t v = nib;
    #pragma unroll
    for (int s = 0; s < 3; ++s) {
        const int step = 1 << s;
        const int w = 4 << s;
        uint32_t other = __shfl_xor_sync(0xffffffffu, v, step);
        v = (lane & step) ? ((v << w) | other) : (v | (other << w));
    }
    if ((lane & 7) == 0) g_qw[b * NWORDS + 4 * warp + (lane >> 3)] = v;
    if (warp == 0 && lane == 0) g_sq[b] = f.x;
}

// ============================================================================
// 1) main: candidate-pack + popcount sim + per-chunk max-ord selection.
//    occ 4 (waves 1.76 -> 1.32) + explicit-MLP row loading (8 LDG.128 in
//    flight before any shuffle chain).
// ============================================================================
__global__ void __launch_bounds__(256, 4)
main_kernel(const float* __restrict__ ev, const int* __restrict__ qrel,
            float* __restrict__ out) {
    __shared__ uint32_t cws[NWORDS * CSTRIDE];   // candidate bitmaps (transposed)
    __shared__ float    snm[CAND];
    __shared__ uint32_t qsm[BATCH * NWORDS];
    __shared__ float    sqm[BATCH];
    __shared__ int      relwS[BATCH];
    __shared__ uint32_t relshS[BATCH];
    __shared__ uint32_t wkey[BATCH * 8];         // per-warp max ord

    const int tid  = threadIdx.x;
    const int warp = tid >> 5;
    const int lane = tid & 31;

    // stage query data (g_qw/g_sq from qpack; 4 KB exact)
    ((uint4*)qsm)[tid] = ((const uint4*)g_qw)[tid];
    if (tid < BATCH) {
        sqm[tid] = g_sq[tid];
        int rr = qrel[tid];
        relwS[tid]  = rr >> 5;
        relshS[tid] = (uint32_t)(rr & 31);
    }

    // ---- phase A: pack 32 rows per warp, 2 rows in flight (MLP = 8) ----
    const int row0 = blockIdx.x * CAND + warp * 32;
    for (int j0 = 0; j0 < 32; j0 += 2) {
        const int ra = row0 + j0, rb = row0 + j0 + 1;
        float4 fa[4], fb[4];
        load_row_f4(ev + (size_t)ra * N_REL, ra < N_ENT, lane, fa);
        load_row_f4(ev + (size_t)rb * N_REL, rb < N_ENT, lane, fb);
        uint32_t va[4], vb[4];
        pack_row_regs(fa, lane, va);
        pack_row_regs(fb, lane, vb);
        if ((lane & 7) == 0) {
            const int g = lane >> 3;
            #pragma unroll
            for (int c = 0; c < 4; ++c) {
                cws[(4 * c + g) * CSTRIDE + warp * 32 + j0]     = va[c];
                cws[(4 * c + g) * CSTRIDE + warp * 32 + j0 + 1] = vb[c];
            }
        }
        if (lane == 0) {
            snm[warp * 32 + j0]     = fa[0].x;
            snm[warp * 32 + j0 + 1] = fb[0].x;
        }
    }
    __syncthreads();

    // ---- phase B: 64-query popcount + selection ----
    const int n = blockIdx.x * CAND + tid;
    const bool valid = (n < N_ENT);
    uint32_t cw[NWORDS];
    #pragma unroll
    for (int w = 0; w < NWORDS; ++w) cw[w] = cws[w * CSTRIDE + tid];
    const float sn = snm[tid];
    const int wordIdx = n >> 5;     // warp-uniform

    #pragma unroll 4
    for (int b = 0; b < BATCH; ++b) {
        const uint4* q4 = (const uint4*)(qsm + b * NWORDS);
        int cnt = 0;
        #pragma unroll
        for (int g = 0; g < 4; ++g) {
            uint4 q = q4[g];
            cnt += __popc(cw[g*4+0] & q.x) + __popc(cw[g*4+1] & q.y)
                 + __popc(cw[g*4+2] & q.z) + __popc(cw[g*4+3] & q.w);
        }
        float val = __fmul_rn(__fmul_rn((float)cnt, sn), sqm[b]);
        uint32_t kw = cws[relwS[b] * CSTRIDE + tid];
        uint32_t kb = (kw >> relshS[b]) & 1u;        // invalid rows: words are 0
        uint32_t bal = __ballot_sync(0xffffffffu, kb);

        // branchless ord; per-warp max (index recovered later by rescan)
        uint32_t ord  = (__float_as_uint(val) | 0x80000000u) & (0u - kb);
        uint32_t wmax = __reduce_max_sync(0xffffffffu, ord);
        if (lane == 0) wkey[b * 8 + warp] = wmax;

        if (valid) {
            out[(size_t)b * N_ENT + n] = val;                 // coalesced
            if (lane == 0) g_mask[(size_t)b * MASKW + wordIdx] = bal;
        }
    }
    __syncthreads();

    if (tid < BATCH) {
        uint32_t m = wkey[tid * 8];
        #pragma unroll
        for (int w = 1; w < 8; ++w) m = u32max_(m, wkey[tid * 8 + w]);
        g_cmax[(size_t)tid * NCHUNKS + blockIdx.x] = m;
    }
}

// ============================================================================
// 2) final: per query (64 CTAs): rank chunks by (maxord, smaller-id-first);
//    rescan the 16 surviving chunks (4K sims, L2-hot); compact ord >= tau;
//    exact rank-select on full (ord, ~idx) keys; write output.
// ============================================================================
__global__ void __launch_bounds__(512)
final_kernel(const float* __restrict__ sim, const int* __restrict__ kptr,
             float* __restrict__ out) {
    __shared__ uint32_t ck[NCHUNKS];
    __shared__ unsigned long long sbuf[FCAP];
    __shared__ unsigned long long spart[MAXK];
    __shared__ uint32_t stau;
    __shared__ int chunkIds[MAXK];
    __shared__ int scnt;

    const int b   = blockIdx.x;
    const int tid = threadIdx.x;

    for (int i = tid; i < NCHUNKS; i += 512)
        ck[i] = g_cmax[(size_t)b * NCHUNKS + i];
    if (tid == 0) scnt = 0;
    __syncthreads();

    // rank chunks by key = (maxord << 32) | ~id  (unique)
    for (int i = tid; i < NCHUNKS; i += 512) {
        unsigned long long key = ((unsigned long long)ck[i] << 32) | (uint32_t)(~i);
        int rank = 0;
        for (int j = 0; j < NCHUNKS; ++j) {
            unsigned long long kj = ((unsigned long long)ck[j] << 32) | (uint32_t)(~j);
            rank += (kj > key);
        }
        if (rank == MAXK - 1) stau = ck[i];
        if (rank < MAXK) chunkIds[rank] = i;
    }
    __syncthreads();
    const uint32_t tau = stau;

    // rescan the 16 surviving chunks; compact elements with ord >= tau
    const float*    row  = sim + (size_t)b * N_ENT;
    const uint32_t* mrow = g_mask + (size_t)b * MASKW;
    for (int e = tid; e < MAXK * CAND; e += 512) {
        int c = chunkIds[e >> 8];
        int n = c * CAND + (e & 255);
        if (n < N_ENT) {
            float x = row[n];
            uint32_t kb = (mrow[n >> 5] >> (n & 31)) & 1u;
            uint32_t ord = (__float_as_uint(x) | 0x80000000u) & (0u - kb);
            if (ord >= tau) {
                int p = atomicAdd(&scnt, 1);
                sbuf[p] = ((unsigned long long)ord << 32) | (uint32_t)(~n);
            }
        }
    }
    __syncthreads();
    const int cnt = scnt;    // >= 16 guaranteed (each selected chunk's max >= tau)

    for (int i = tid; i < cnt; i += 512) {
        unsigned long long key = sbuf[i];
        int rank = 0;
        for (int j = 0; j < cnt; ++j) rank += (sbuf[j] > key);
        if (rank < MAXK) spart[rank] = key;
    }
    __syncthreads();

    if (tid == 0) {
        int kk = kptr[0] + 5;                 // k + K_EXTRA
        if (kk > MAXK) kk = MAXK;
        const float NEG_INF = __int_as_float(0xFF800000);
        size_t obase = (size_t)BATCH * N_ENT;
        float* out_v = out + obase + (size_t)b * kk;
        float* out_i = out + obase + (size_t)BATCH * kk + (size_t)b * kk;
        for (int j = 0; j < kk; ++j) {
            unsigned long long key = spart[j];
            uint32_t hi = (uint32_t)(key >> 32);
            out_v[j] = (hi & 0x80000000u) ? __uint_as_float(hi ^ 0x80000000u)
                                          : NEG_INF;
            out_i[j] = (float)(int)(~(uint32_t)key);
        }
    }
}

// ============================================================================
extern "C" void kernel_launch(void* const* d_in, const int* in_sizes, int n_in,
                              void* d_out, int out_size) {
    const float* ev   = (const float*)d_in[0];
    const int*   qe   = (const int*)d_in[1];
    const int*   qr   = (const int*)d_in[2];
    const int*   kptr = (const int*)d_in[3];
    float* out = (float*)d_out;

    qpack_kernel<<<BATCH, 128>>>(ev, qe);                // 64 CTAs
    main_kernel<<<NCHUNKS, 256>>>(ev, qr, out);          // 782 CTAs
    final_kernel<<<BATCH, 512>>>(out, kptr, out);        // 64 CTAs
}

// round 11
// speedup vs baseline: 1.0353x; 1.0353x over previous
#include <cuda_runtime.h>
#include <cstdint>

// Problem-instance constants (fixed by setup_inputs)
#define N_ENT   200000
#define N_REL   500
#define BATCH   64
#define NWORDS  16                 // 512 bits >= 500 relations
#define MASKW   (N_ENT / 32)       // 6250 mask words per query
#define MAXK    16
#define CAND    256                // candidates per main CTA
#define NCHUNKS ((N_ENT + CAND - 1) / CAND)   // 782
#define CSTRIDE 257                // padded smem stride
#define FCAP    4096               // final survivor buffer (= full rescan size)

// ---------------- device scratch (no allocations allowed) ----------------
__device__ uint32_t g_qw[BATCH * NWORDS];            // query bitmaps
__device__ float    g_sq[BATCH];                     // s_q
__device__ uint32_t g_mask[(size_t)BATCH * MASKW];   // keep bits
__device__ uint32_t g_cmax[(size_t)BATCH * NCHUNKS]; // chunk-max ord (u32)

// ord = keep ? bits|0x80000000 : 0   (vals >= 0, so this is order-preserving)
__device__ __forceinline__ uint32_t u32max_(uint32_t a, uint32_t b) {
    return a > b ? a : b;
}

// Pack one row's chunk c (128 elems) into 4 words via nibble+butterfly.
// Streaming load (.cs): ev has zero reuse — don't pollute L1.
__device__ __forceinline__ uint32_t pack_chunk(const float* __restrict__ row,
                                               int c, int lane, bool rowValid,
                                               float* s0out) {
    const int e = c * 128 + lane * 4;
    float4 f = make_float4(0.f, 0.f, 0.f, 0.f);
    if (rowValid && e + 3 < N_REL)
        f = __ldcs((const float4*)(row + e));
    if (c == 0 && lane == 0) *s0out = f.x;     // ev[r,0]
    uint32_t nib = (f.x != 0.0f ? 1u : 0u) | (f.y != 0.0f ? 2u : 0u)
                 | (f.z != 0.0f ? 4u : 0u) | (f.w != 0.0f ? 8u : 0u);
    uint32_t v = nib;
    #pragma unroll
    for (int s = 0; s < 3; ++s) {
        const int step = 1 << s;
        const int w = 4 << s;
        uint32_t other = __shfl_xor_sync(0xffffffffu, v, step);
        v = (lane & step) ? ((v << w) | other) : (v | (other << w));
    }
    return v;
}

// ============================================================================
// 0) qpack: 64 CTAs x 128 threads; warp c packs chunk c of the query row.
// ============================================================================
__global__ void __launch_bounds__(128)
qpack_kernel(const float* __restrict__ ev, const int* __restrict__ qent) {
    const int b    = blockIdx.x;
    const int warp = threadIdx.x >> 5;
    const int lane = threadIdx.x & 31;
    const float* row = ev + (size_t)qent[b] * N_REL;
    float s0 = 0.0f;
    uint32_t v = pack_chunk(row, warp, lane, true, &s0);
    if ((lane & 7) == 0) g_qw[b * NWORDS + 4 * warp + (lane >> 3)] = v;
    if (warp == 0 && lane == 0) g_sq[b] = s0;
}

// ============================================================================
// 1) main: candidate-pack + popcount sim + per-chunk max-ord selection.
//    Exact R9-best config (occ 3, unroll 4, u32 selection) + streaming
//    cache policy on the 400 MB ev read and 51 MB sim write.
// ============================================================================
__global__ void __launch_bounds__(256, 3)
main_kernel(const float* __restrict__ ev, const int* __restrict__ qrel,
            float* __restrict__ out) {
    __shared__ uint32_t cws[NWORDS * CSTRIDE];   // candidate bitmaps (transposed)
    __shared__ float    snm[CAND];
    __shared__ uint32_t qsm[BATCH * NWORDS];
    __shared__ float    sqm[BATCH];
    __shared__ int      relwS[BATCH];
    __shared__ uint32_t relshS[BATCH];
    __shared__ uint32_t wkey[BATCH * 8];         // per-warp max ord

    const int tid  = threadIdx.x;
    const int warp = tid >> 5;
    const int lane = tid & 31;

    // stage query data (g_qw/g_sq from qpack; 4 KB exact)
    ((uint4*)qsm)[tid] = ((const uint4*)g_qw)[tid];
    if (tid < BATCH) {
        sqm[tid] = g_sq[tid];
        int rr = qrel[tid];
        relwS[tid]  = rr >> 5;
        relshS[tid] = (uint32_t)(rr & 31);
    }

    // ---- phase A: pack 32 candidate rows per warp ----
    const int row0 = blockIdx.x * CAND + warp * 32;
    #pragma unroll 4
    for (int j = 0; j < 32; ++j) {
        const int r = row0 + j;
        const bool rv = (r < N_ENT);
        const float* row = ev + (size_t)r * N_REL;
        float s0 = 0.0f;
        #pragma unroll
        for (int c = 0; c < 4; ++c) {
            uint32_t v = pack_chunk(row, c, lane, rv, &s0);
            if ((lane & 7) == 0)
                cws[(4 * c + (lane >> 3)) * CSTRIDE + warp * 32 + j] = v;
        }
        if (lane == 0) snm[warp * 32 + j] = s0;
    }
    __syncthreads();

    // ---- phase B: 64-query popcount + selection ----
    const int n = blockIdx.x * CAND + tid;
    const bool valid = (n < N_ENT);
    uint32_t cw[NWORDS];
    #pragma unroll
    for (int w = 0; w < NWORDS; ++w) cw[w] = cws[w * CSTRIDE + tid];
    const float sn = snm[tid];
    const int wordIdx = n >> 5;     // warp-uniform

    #pragma unroll 4
    for (int b = 0; b < BATCH; ++b) {
        const uint4* q4 = (const uint4*)(qsm + b * NWORDS);
        int cnt = 0;
        #pragma unroll
        for (int g = 0; g < 4; ++g) {
            uint4 q = q4[g];
            cnt += __popc(cw[g*4+0] & q.x) + __popc(cw[g*4+1] & q.y)
                 + __popc(cw[g*4+2] & q.z) + __popc(cw[g*4+3] & q.w);
        }
        float val = __fmul_rn(__fmul_rn((float)cnt, sn), sqm[b]);
        uint32_t kw = cws[relwS[b] * CSTRIDE + tid];
        uint32_t kb = (kw >> relshS[b]) & 1u;        // invalid rows: words are 0
        uint32_t bal = __ballot_sync(0xffffffffu, kb);

        // branchless ord; per-warp max (index recovered later by rescan)
        uint32_t ord  = (__float_as_uint(val) | 0x80000000u) & (0u - kb);
        uint32_t wmax = __reduce_max_sync(0xffffffffu, ord);
        if (lane == 0) wkey[b * 8 + warp] = wmax;

        if (valid) {
            __stcs(out + (size_t)b * N_ENT + n, val);          // streaming store
            if (lane == 0) g_mask[(size_t)b * MASKW + wordIdx] = bal;
        }
    }
    __syncthreads();

    if (tid < BATCH) {
        uint32_t m = wkey[tid * 8];
        #pragma unroll
        for (int w = 1; w < 8; ++w) m = u32max_(m, wkey[tid * 8 + w]);
        g_cmax[(size_t)tid * NCHUNKS + blockIdx.x] = m;
    }
}

// ============================================================================
// 2) final: per query (64 CTAs): rank chunks by (maxord, smaller-id-first);
//    rescan the 16 surviving chunks (4K sims, L2-hot); compact ord >= tau;
//    exact rank-select on full (ord, ~idx) keys; write output.
// ============================================================================
__global__ void __launch_bounds__(512)
final_kernel(const float* __restrict__ sim, const int* __restrict__ kptr,
             float* __restrict__ out) {
    __shared__ uint32_t ck[NCHUNKS];
    __shared__ unsigned long long sbuf[FCAP];
    __shared__ unsigned long long spart[MAXK];
    __shared__ uint32_t stau;
    __shared__ int chunkIds[MAXK];
    __shared__ int scnt;

    const int b   = blockIdx.x;
    const int tid = threadIdx.x;

    for (int i = tid; i < NCHUNKS; i += 512)
        ck[i] = g_cmax[(size_t)b * NCHUNKS + i];
    if (tid == 0) scnt = 0;
    __syncthreads();

    // rank chunks by key = (maxord << 32) | ~id  (unique)
    for (int i = tid; i < NCHUNKS; i += 512) {
        unsigned long long key = ((unsigned long long)ck[i] << 32) | (uint32_t)(~i);
        int rank = 0;
        for (int j = 0; j < NCHUNKS; ++j) {
            unsigned long long kj = ((unsigned long long)ck[j] << 32) | (uint32_t)(~j);
            rank += (kj > key);
        }
        if (rank == MAXK - 1) stau = ck[i];
        if (rank < MAXK) chunkIds[rank] = i;
    }
    __syncthreads();
    const uint32_t tau = stau;

    // rescan the 16 surviving chunks; compact elements with ord >= tau
    const float*    row  = sim + (size_t)b * N_ENT;
    const uint32_t* mrow = g_mask + (size_t)b * MASKW;
    for (int e = tid; e < MAXK * CAND; e += 512) {
        int c = chunkIds[e >> 8];
        int n = c * CAND + (e & 255);
        if (n < N_ENT) {
            float x = row[n];
            uint32_t kb = (mrow[n >> 5] >> (n & 31)) & 1u;
            uint32_t ord = (__float_as_uint(x) | 0x80000000u) & (0u - kb);
            if (ord >= tau) {
                int p = atomicAdd(&scnt, 1);
                sbuf[p] = ((unsigned long long)ord << 32) | (uint32_t)(~n);
            }
        }
    }
    __syncthreads();
    const int cnt = scnt;    // >= 16 guaranteed (each selected chunk's max >= tau)

    for (int i = tid; i < cnt; i += 512) {
        unsigned long long key = sbuf[i];
        int rank = 0;
        for (int j = 0; j < cnt; ++j) rank += (sbuf[j] > key);
        if (rank < MAXK) spart[rank] = key;
    }
    __syncthreads();

    if (tid == 0) {
        int kk = kptr[0] + 5;                 // k + K_EXTRA
        if (kk > MAXK) kk = MAXK;
        const float NEG_INF = __int_as_float(0xFF800000);
        size_t obase = (size_t)BATCH * N_ENT;
        float* out_v = out + obase + (size_t)b * kk;
        float* out_i = out + obase + (size_t)BATCH * kk + (size_t)b * kk;
        for (int j = 0; j < kk; ++j) {
            unsigned long long key = spart[j];
            uint32_t hi = (uint32_t)(key >> 32);
            out_v[j] = (hi & 0x80000000u) ? __uint_as_float(hi ^ 0x80000000u)
                                          : NEG_INF;
            out_i[j] = (float)(int)(~(uint32_t)key);
        }
    }
}

// ============================================================================
extern "C" void kernel_launch(void* const* d_in, const int* in_sizes, int n_in,
                              void* d_out, int out_size) {
    const float* ev   = (const float*)d_in[0];
    const int*   qe   = (const int*)d_in[1];
    const int*   qr   = (const int*)d_in[2];
    const int*   kptr = (const int*)d_in[3];
    float* out = (float*)d_out;

    qpack_kernel<<<BATCH, 128>>>(ev, qe);                // 64 CTAs
    main_kernel<<<NCHUNKS, 256>>>(ev, qr, out);          // 782 CTAs
    final_kernel<<<BATCH, 512>>>(out, kptr, out);        // 64 CTAs
}

// round 12
// speedup vs baseline: 1.0381x; 1.0027x over previous
#include <cuda_runtime.h>
#include <cstdint>

// Problem-instance constants (fixed by setup_inputs)
#define N_ENT   200000
#define N_REL   500
#define BATCH   64
#define NWORDS  16                 // 512 bits >= 500 relations
#define MASKW   (N_ENT / 32)       // 6250 mask words per query
#define MAXK    16
#define CAND    256                // candidates per main CTA
#define NCHUNKS ((N_ENT + CAND - 1) / CAND)   // 782
#define CSTRIDE 258                // padded smem stride (conflict-free both phases)
#define FCAP    4096               // final survivor buffer (= full rescan size)

// Bit permutation: relation e lives in word W(e) = (e>>2)&15 at bit
// B(e) = 4*(e>>6) + (e&3). popc(AND) is invariant under this global remap;
// the keep-bit lookup uses (W,B) of the query relation.

// ---------------- device scratch (no allocations allowed) ----------------
__device__ uint32_t g_qw[BATCH * NWORDS];            // query bitmaps (permuted)
__device__ float    g_sq[BATCH];                     // s_q
__device__ uint32_t g_mask[(size_t)BATCH * MASKW];   // keep bits
__device__ uint32_t g_cmax[(size_t)BATCH * NCHUNKS]; // chunk-max ord (u32)

__device__ __forceinline__ uint32_t u32max_(uint32_t a, uint32_t b) {
    return a > b ? a : b;
}

// Pack one row's word t (t = 0..15) from 8 strided float4s; no shuffles.
// f[i] = float4 #(i*16 + t) of the row (elements 64i+4t .. 64i+4t+3).
__device__ __forceinline__ uint32_t pack_word(const float* __restrict__ rowp,
                                              bool rowValid, int t, float* e0) {
    float4 f[8];
    #pragma unroll
    for (int i = 0; i < 8; ++i) {
        const int q = i * 16 + t;
        if (rowValid && 4 * q + 3 < N_REL)
            f[i] = __ldcs((const float4*)rowp + q);
        else
            f[i] = make_float4(0.f, 0.f, 0.f, 0.f);
    }
    uint32_t word = 0;
    #pragma unroll
    for (int i = 0; i < 8; ++i) {
        word |= (f[i].x != 0.0f ? (1u << (4 * i)) : 0u);
        word |= (f[i].y != 0.0f ? (2u << (4 * i)) : 0u);
        word |= (f[i].z != 0.0f ? (4u << (4 * i)) : 0u);
        word |= (f[i].w != 0.0f ? (8u << (4 * i)) : 0u);
    }
    *e0 = f[0].x;        // for t==0 this is ev[r,0]
    return word;
}

// ============================================================================
// 0) qpack: 64 CTAs x 16 threads; thread t packs word t of the query row.
// ============================================================================
__global__ void __launch_bounds__(16)
qpack_kernel(const float* __restrict__ ev, const int* __restrict__ qent) {
    const int b = blockIdx.x;
    const int t = threadIdx.x;            // 0..15
    const float* row = ev + (size_t)qent[b] * N_REL;
    float e0;
    uint32_t w = pack_word(row, true, t, &e0);
    g_qw[b * NWORDS + t] = w;
    if (t == 0) g_sq[b] = e0;
}

// ============================================================================
// 1) main: shuffle-free candidate-pack (MLP 8/thread) + popcount sim +
//    per-chunk max-ord selection.  occ 3 (measured best).
// ============================================================================
__global__ void __launch_bounds__(256, 3)
main_kernel(const float* __restrict__ ev, const int* __restrict__ qrel,
            float* __restrict__ out) {
    __shared__ uint32_t cws[NWORDS * CSTRIDE];   // candidate bitmaps (transposed)
    __shared__ float    snm[CAND];
    __shared__ uint32_t qsm[BATCH * NWORDS];
    __shared__ float    sqm[BATCH];
    __shared__ int      relwS[BATCH];
    __shared__ uint32_t relshS[BATCH];
    __shared__ uint32_t wkey[BATCH * 8];         // per-warp max ord

    const int tid  = threadIdx.x;
    const int warp = tid >> 5;
    const int lane = tid & 31;

    // stage query data (g_qw/g_sq from qpack; 4 KB exact)
    ((uint4*)qsm)[tid] = ((const uint4*)g_qw)[tid];
    if (tid < BATCH) {
        sqm[tid] = g_sq[tid];
        int rr = qrel[tid];
        relwS[tid]  = (rr >> 2) & 15;                          // W(rr)
        relshS[tid] = (uint32_t)(4 * (rr >> 6) + (rr & 3));    // B(rr)
    }

    // ---- phase A: pack; warp = 2 rows x 16 words per pass, 16 passes ----
    const int grp = lane >> 4;     // row within warp pair (0/1)
    const int t16 = lane & 15;     // word index owned by this thread
    const int row0 = blockIdx.x * CAND;
    for (int pass = 0; pass < 16; ++pass) {
        const int rlocal = pass * 16 + warp * 2 + grp;
        const int r = row0 + rlocal;
        float e0;
        uint32_t w = pack_word(ev + (size_t)r * N_REL, r < N_ENT, t16, &e0);
        cws[t16 * CSTRIDE + rlocal] = w;
        if (t16 == 0) snm[rlocal] = e0;
    }
    __syncthreads();

    // ---- phase B: 64-query popcount + selection ----
    const int n = blockIdx.x * CAND + tid;
    const bool valid = (n < N_ENT);
    uint32_t cw[NWORDS];
    #pragma unroll
    for (int w = 0; w < NWORDS; ++w) cw[w] = cws[w * CSTRIDE + tid];
    const float sn = snm[tid];
    const int wordIdx = n >> 5;     // warp-uniform

    #pragma unroll 4
    for (int b = 0; b < BATCH; ++b) {
        const uint4* q4 = (const uint4*)(qsm + b * NWORDS);
        int cnt = 0;
        #pragma unroll
        for (int g = 0; g < 4; ++g) {
            uint4 q = q4[g];
            cnt += __popc(cw[g*4+0] & q.x) + __popc(cw[g*4+1] & q.y)
                 + __popc(cw[g*4+2] & q.z) + __popc(cw[g*4+3] & q.w);
        }
        float val = __fmul_rn(__fmul_rn((float)cnt, sn), sqm[b]);
        uint32_t kw = cws[relwS[b] * CSTRIDE + tid];
        uint32_t kb = (kw >> relshS[b]) & 1u;        // invalid rows: words are 0
        uint32_t bal = __ballot_sync(0xffffffffu, kb);

        // branchless ord; per-warp max (index recovered later by rescan)
        uint32_t ord  = (__float_as_uint(val) | 0x80000000u) & (0u - kb);
        uint32_t wmax = __reduce_max_sync(0xffffffffu, ord);
        if (lane == 0) wkey[b * 8 + warp] = wmax;

        if (valid) {
            __stcs(out + (size_t)b * N_ENT + n, val);          // streaming store
            if (lane == 0) g_mask[(size_t)b * MASKW + wordIdx] = bal;
        }
    }
    __syncthreads();

    if (tid < BATCH) {
        uint32_t m = wkey[tid * 8];
        #pragma unroll
        for (int w = 1; w < 8; ++w) m = u32max_(m, wkey[tid * 8 + w]);
        g_cmax[(size_t)tid * NCHUNKS + blockIdx.x] = m;
    }
}

// ============================================================================
// 2) final: per query (64 CTAs): rank chunks by (maxord, smaller-id-first);
//    rescan the 16 surviving chunks (4K sims, L2-hot); compact ord >= tau;
//    exact rank-select on full (ord, ~idx) keys; write output.
// ============================================================================
__global__ void __launch_bounds__(512)
final_kernel(const float* __restrict__ sim, const int* __restrict__ kptr,
             float* __restrict__ out) {
    __shared__ uint32_t ck[NCHUNKS];
    __shared__ unsigned long long sbuf[FCAP];
    __shared__ unsigned long long spart[MAXK];
    __shared__ uint32_t stau;
    __shared__ int chunkIds[MAXK];
    __shared__ int scnt;

    const int b   = blockIdx.x;
    const int tid = threadIdx.x;

    for (int i = tid; i < NCHUNKS; i += 512)
        ck[i] = g_cmax[(size_t)b * NCHUNKS + i];
    if (tid == 0) scnt = 0;
    __syncthreads();

    // rank chunks by key = (maxord << 32) | ~id  (unique)
    for (int i = tid; i < NCHUNKS; i += 512) {
        unsigned long long key = ((unsigned long long)ck[i] << 32) | (uint32_t)(~i);
        int rank = 0;
        for (int j = 0; j < NCHUNKS; ++j) {
            unsigned long long kj = ((unsigned long long)ck[j] << 32) | (uint32_t)(~j);
            rank += (kj > key);
        }
        if (rank == MAXK - 1) stau = ck[i];
        if (rank < MAXK) chunkIds[rank] = i;
    }
    __syncthreads();
    const uint32_t tau = stau;

    // rescan the 16 surviving chunks; compact elements with ord >= tau
    const float*    row  = sim + (size_t)b * N_ENT;
    const uint32_t* mrow = g_mask + (size_t)b * MASKW;
    for (int e = tid; e < MAXK * CAND; e += 512) {
        int c = chunkIds[e >> 8];
        int n = c * CAND + (e & 255);
        if (n < N_ENT) {
            float x = row[n];
            uint32_t kb = (mrow[n >> 5] >> (n & 31)) & 1u;
            uint32_t ord = (__float_as_uint(x) | 0x80000000u) & (0u - kb);
            if (ord >= tau) {
                int p = atomicAdd(&scnt, 1);
                sbuf[p] = ((unsigned long long)ord << 32) | (uint32_t)(~n);
            }
        }
    }
    __syncthreads();
    const int cnt = scnt;    // >= 16 guaranteed (each selected chunk's max >= tau)

    for (int i = tid; i < cnt; i += 512) {
        unsigned long long key = sbuf[i];
        int rank = 0;
        for (int j = 0; j < cnt; ++j) rank += (sbuf[j] > key);
        if (rank < MAXK) spart[rank] = key;
    }
    __syncthreads();

    if (tid == 0) {
        int kk = kptr[0] + 5;                 // k + K_EXTRA
        if (kk > MAXK) kk = MAXK;
        const float NEG_INF = __int_as_float(0xFF800000);
        size_t obase = (size_t)BATCH * N_ENT;
        float* out_v = out + obase + (size_t)b * kk;
        float* out_i = out + obase + (size_t)BATCH * kk + (size_t)b * kk;
        for (int j = 0; j < kk; ++j) {
            unsigned long long key = spart[j];
            uint32_t hi = (uint32_t)(key >> 32);
            out_v[j] = (hi & 0x80000000u) ? __uint_as_float(hi ^ 0x80000000u)
                                          : NEG_INF;
            out_i[j] = (float)(int)(~(uint32_t)key);
        }
    }
}

// ============================================================================
extern "C" void kernel_launch(void* const* d_in, const int* in_sizes, int n_in,
                              void* d_out, int out_size) {
    const float* ev   = (const float*)d_in[0];
    const int*   qe   = (const int*)d_in[1];
    const int*   qr   = (const int*)d_in[2];
    const int*   kptr = (const int*)d_in[3];
    float* out = (float*)d_out;

    qpack_kernel<<<BATCH, 16>>>(ev, qe);                 // 64 CTAs
    main_kernel<<<NCHUNKS, 256>>>(ev, qr, out);          // 782 CTAs
    final_kernel<<<BATCH, 512>>>(out, kptr, out);        // 64 CTAs
}

// round 13
// speedup vs baseline: 1.0774x; 1.0379x over previous
#include <cuda_runtime.h>
#include <cstdint>

// Problem-instance constants (fixed by setup_inputs)
#define N_ENT   200000
#define N_REL   500
#define BATCH   64
#define NWORDS  16                 // 512 bits >= 500 relations
#define MASKW   (N_ENT / 32)       // 6250 mask words per query
#define MAXK    16
#define CAND    256                // candidates per chunk
#define NCHUNKS ((N_ENT + CAND - 1) / CAND)   // 782
#define NBLK    ((NCHUNKS + 1) / 2)           // 391 CTAs, 2 chunks each
#define CSTRIDE 258                // padded smem stride
#define FCAP    4096               // final survivor buffer

// Bit permutation: relation e lives in word W(e) = (e>>2)&15 at bit
// B(e) = 4*(e>>6) + (e&3). popc(AND) invariant; keep-bit uses (W,B).

// ---------------- device scratch (no allocations allowed) ----------------
__device__ uint32_t g_qw[BATCH * NWORDS];            // query bitmaps (permuted)
__device__ float    g_sq[BATCH];                     // s_q
__device__ uint32_t g_mask[(size_t)BATCH * MASKW];   // keep bits
__device__ uint32_t g_cmax[(size_t)BATCH * NCHUNKS]; // chunk-max ord (u32)
__device__ int      g_spacer;                        // profiler steering

__device__ __forceinline__ uint32_t u32max_(uint32_t a, uint32_t b) {
    return a > b ? a : b;
}

// Load the 8 strided float4s for word t of a row (no dependence chain).
__device__ __forceinline__ void load_word_f4(const float* __restrict__ rowp,
                                             bool rowValid, int t, float4 f[8]) {
    #pragma unroll
    for (int i = 0; i < 8; ++i) {
        const int q = i * 16 + t;
        if (rowValid && 4 * q + 3 < N_REL)
            f[i] = __ldcs((const float4*)rowp + q);
        else
            f[i] = make_float4(0.f, 0.f, 0.f, 0.f);
    }
}
__device__ __forceinline__ uint32_t binarize_word(const float4 f[8]) {
    uint32_t word = 0;
    #pragma unroll
    for (int i = 0; i < 8; ++i) {
        word |= (f[i].x != 0.0f ? (1u << (4 * i)) : 0u);
        word |= (f[i].y != 0.0f ? (2u << (4 * i)) : 0u);
        word |= (f[i].z != 0.0f ? (4u << (4 * i)) : 0u);
        word |= (f[i].w != 0.0f ? (8u << (4 * i)) : 0u);
    }
    return word;
}

// ============================================================================
// 0) qpack: 64 CTAs x 16 threads; thread t packs word t of the query row.
// ============================================================================
__global__ void __launch_bounds__(16)
qpack_kernel(const float* __restrict__ ev, const int* __restrict__ qent) {
    const int b = blockIdx.x;
    const int t = threadIdx.x;            // 0..15
    float4 f[8];
    load_word_f4(ev + (size_t)qent[b] * N_REL, true, t, f);
    g_qw[b * NWORDS + t] = binarize_word(f);
    if (t == 0) g_sq[b] = f[0].x;         // ev[qe,0]
}

// spacers: position main at global launch index 3 for ncu
__global__ void spacer1_kernel() { g_spacer = 1; }
__global__ void spacer2_kernel() { g_spacer = 2; }

// ============================================================================
// 1) main (pipelined): 391 CTAs x 2 chunks. Chunk i+1's global loads are
//    interleaved with chunk i's popcount groups to keep DRAM continuously
//    busy (breaks the phase-lockstep duty cycle). Single wave at occ 3.
// ============================================================================
__shared__ uint32_t sh_cws[2][NWORDS * CSTRIDE];
__shared__ float    sh_snm[2][CAND];
__shared__ uint32_t sh_qsm[BATCH * NWORDS];
__shared__ float    sh_sqm[BATCH];
__shared__ int      sh_relw[BATCH];
__shared__ uint32_t sh_rels[BATCH];
__shared__ uint32_t sh_wkey[BATCH * 8];

template <bool PREFETCH>
__device__ __forceinline__ void process_chunk(
    int cid, int nextBase, int tid, int warp, int lane, int grp, int t16,
    const float* __restrict__ ev, float* __restrict__ out, int buf) {
    const int n = cid * CAND + tid;
    const bool valid = (n < N_ENT);
    uint32_t cw[NWORDS];
    #pragma unroll
    for (int w = 0; w < NWORDS; ++w) cw[w] = sh_cws[buf][w * CSTRIDE + tid];
    const float sn = sh_snm[buf][tid];
    const int wordIdx = n >> 5;     // warp-uniform

    const int rlbase = warp * 2 + grp;

    for (int gq = 0; gq < 16; ++gq) {
        // prefetch next chunk's pass gq (8 independent LDG.128)
        float4 f[8];
        int rlocal = gq * 16 + rlbase;
        if (PREFETCH) {
            int rn = nextBase + rlocal;
            load_word_f4(ev + (size_t)rn * N_REL, rn < N_ENT, t16, f);
        }

        // 4 queries of popcount + selection for the current chunk
        #pragma unroll
        for (int bq = 0; bq < 4; ++bq) {
            const int b = gq * 4 + bq;
            const uint4* q4 = (const uint4*)(sh_qsm + b * NWORDS);
            int cnt = 0;
            #pragma unroll
            for (int g = 0; g < 4; ++g) {
                uint4 q = q4[g];
                cnt += __popc(cw[g*4+0] & q.x) + __popc(cw[g*4+1] & q.y)
                     + __popc(cw[g*4+2] & q.z) + __popc(cw[g*4+3] & q.w);
            }
            float val = __fmul_rn(__fmul_rn((float)cnt, sn), sh_sqm[b]);
            uint32_t kw = sh_cws[buf][sh_relw[b] * CSTRIDE + tid];
            uint32_t kb = (kw >> sh_rels[b]) & 1u;
            uint32_t bal = __ballot_sync(0xffffffffu, kb);
            uint32_t ord = (__float_as_uint(val) | 0x80000000u) & (0u - kb);
            uint32_t wmax = __reduce_max_sync(0xffffffffu, ord);
            if (lane == 0) sh_wkey[b * 8 + warp] = wmax;
            if (valid) {
                __stcs(out + (size_t)b * N_ENT + n, val);
                if (lane == 0) g_mask[(size_t)b * MASKW + wordIdx] = bal;
            }
        }

        if (PREFETCH) {
            sh_cws[buf ^ 1][t16 * CSTRIDE + rlocal] = binarize_word(f);
            if (t16 == 0) sh_snm[buf ^ 1][rlocal] = f[0].x;
        }
    }
    __syncthreads();   // wkey complete (and next buf written if PREFETCH)
    if (tid < BATCH) {
        uint32_t m = sh_wkey[tid * 8];
        #pragma unroll
        for (int w = 1; w < 8; ++w) m = u32max_(m, sh_wkey[tid * 8 + w]);
        g_cmax[(size_t)tid * NCHUNKS + cid] = m;
    }
    __syncthreads();   // wkey free for reuse by the next chunk
}

__global__ void __launch_bounds__(256, 3)
main_kernel(const float* __restrict__ ev, const int* __restrict__ qrel,
            float* __restrict__ out) {
    const int tid  = threadIdx.x;
    const int warp = tid >> 5;
    const int lane = tid & 31;
    const int grp  = lane >> 4;
    const int t16  = lane & 15;

    // stage query data (4 KB exact)
    ((uint4*)sh_qsm)[tid] = ((const uint4*)g_qw)[tid];
    if (tid < BATCH) {
        sh_sqm[tid] = g_sq[tid];
        int rr = qrel[tid];
        sh_relw[tid] = (rr >> 2) & 15;                          // W(rr)
        sh_rels[tid] = (uint32_t)(4 * (rr >> 6) + (rr & 3));    // B(rr)
    }

    const int c0 = blockIdx.x * 2;

    // phase A for chunk 0 into buf 0
    const int rlbase = warp * 2 + grp;
    for (int pass = 0; pass < 16; ++pass) {
        const int rlocal = pass * 16 + rlbase;
        const int r = c0 * CAND + rlocal;
        float4 f[8];
        load_word_f4(ev + (size_t)r * N_REL, r < N_ENT, t16, f);
        sh_cws[0][t16 * CSTRIDE + rlocal] = binarize_word(f);
        if (t16 == 0) sh_snm[0][rlocal] = f[0].x;
    }
    __syncthreads();

    // chunk 0 with prefetch of chunk 1; then chunk 1 (always exists: 782 even)
    process_chunk<true >(c0,     (c0 + 1) * CAND, tid, warp, lane, grp, t16, ev, out, 0);
    process_chunk<false>(c0 + 1, 0,               tid, warp, lane, grp, t16, ev, out, 1);
}

// ============================================================================
// 2) final: per query (64 CTAs): rank chunks by (maxord, smaller-id-first);
//    rescan the 16 surviving chunks; compact ord >= tau; exact rank-select.
// ============================================================================
__global__ void __launch_bounds__(512)
final_kernel(const float* __restrict__ sim, const int* __restrict__ kptr,
             float* __restrict__ out) {
    __shared__ uint32_t ck[NCHUNKS];
    __shared__ unsigned long long sbuf[FCAP];
    __shared__ unsigned long long spart[MAXK];
    __shared__ uint32_t stau;
    __shared__ int chunkIds[MAXK];
    __shared__ int scnt;

    const int b   = blockIdx.x;
    const int tid = threadIdx.x;

    for (int i = tid; i < NCHUNKS; i += 512)
        ck[i] = g_cmax[(size_t)b * NCHUNKS + i];
    if (tid == 0) scnt = 0;
    __syncthreads();

    for (int i = tid; i < NCHUNKS; i += 512) {
        unsigned long long key = ((unsigned long long)ck[i] << 32) | (uint32_t)(~i);
        int rank = 0;
        for (int j = 0; j < NCHUNKS; ++j) {
            unsigned long long kj = ((unsigned long long)ck[j] << 32) | (uint32_t)(~j);
            rank += (kj > key);
        }
        if (rank == MAXK - 1) stau = ck[i];
        if (rank < MAXK) chunkIds[rank] = i;
    }
    __syncthreads();
    const uint32_t tau = stau;

    const float*    row  = sim + (size_t)b * N_ENT;
    const uint32_t* mrow = g_mask + (size_t)b * MASKW;
    for (int e = tid; e < MAXK * CAND; e += 512) {
        int c = chunkIds[e >> 8];
        int n = c * CAND + (e & 255);
        if (n < N_ENT) {
            float x = row[n];
            uint32_t kb = (mrow[n >> 5] >> (n & 31)) & 1u;
            uint32_t ord = (__float_as_uint(x) | 0x80000000u) & (0u - kb);
            if (ord >= tau) {
                int p = atomicAdd(&scnt, 1);
                sbuf[p] = ((unsigned long long)ord << 32) | (uint32_t)(~n);
            }
        }
    }
    __syncthreads();
    const int cnt = scnt;

    for (int i = tid; i < cnt; i += 512) {
        unsigned long long key = sbuf[i];
        int rank = 0;
        for (int j = 0; j < cnt; ++j) rank += (sbuf[j] > key);
        if (rank < MAXK) spart[rank] = key;
    }
    __syncthreads();

    if (tid == 0) {
        int kk = kptr[0] + 5;                 // k + K_EXTRA
        if (kk > MAXK) kk = MAXK;
        const float NEG_INF = __int_as_float(0xFF800000);
        size_t obase = (size_t)BATCH * N_ENT;
        float* out_v = out + obase + (size_t)b * kk;
        float* out_i = out + obase + (size_t)BATCH * kk + (size_t)b * kk;
        for (int j = 0; j < kk; ++j) {
            unsigned long long key = spart[j];
            uint32_t hi = (uint32_t)(key >> 32);
            out_v[j] = (hi & 0x80000000u) ? __uint_as_float(hi ^ 0x80000000u)
                                          : NEG_INF;
            out_i[j] = (float)(int)(~(uint32_t)key);
        }
    }
}

// ============================================================================
extern "C" void kernel_launch(void* const* d_in, const int* in_sizes, int n_in,
                              void* d_out, int out_size) {
    const float* ev   = (const float*)d_in[0];
    const int*   qe   = (const int*)d_in[1];
    const int*   qr   = (const int*)d_in[2];
    const int*   kptr = (const int*)d_in[3];
    float* out = (float*)d_out;

    qpack_kernel<<<BATCH, 16>>>(ev, qe);                 // launch 0
    spacer1_kernel<<<1, 1>>>();                          // launch 1
    spacer2_kernel<<<1, 1>>>();                          // launch 2
    main_kernel<<<NBLK, 256>>>(ev, qr, out);             // launch 3 -> profiled
    final_kernel<<<BATCH, 512>>>(out, kptr, out);        // launch 4
}